// round 17
// baseline (speedup 1.0000x reference)
#include <cuda_runtime.h>

#define TPB   1024
#define NB    128
#define NV    128000
#define NV4   (NV/4)
#define NVH4  (NV4/2)          // 16000 float4 per half-row
#define NL    200
#define HSZ   512
#define HMASK 511
#define NBINS 4096
#define CAPB  3072
#define GCAPB 4096
#define GCAP  512
#define HIW   7.0f
#define LB0   2.1f

// global scratch (device globals are the sanctioned workaround; no allocs)
__device__ unsigned long long g_cand[NB * GCAPB];   // 4 MB base candidates
__device__ unsigned g_cnt[NB];
__device__ float    g_zpart[NB];

struct DynSmem {                                     // K2 dynamic smem (84 KB)
    unsigned hist[NBINS];
    float    whist[NBINS];
    unsigned long long candA[CAPB];
    unsigned long long candB[CAPB];
    unsigned long long gath[GCAP];
};
#define SMEM_DYN ((int)sizeof(DynSmem))

__device__ __forceinline__ float hlookup(int idx, const int* hkey, const float* hval) {
    unsigned h = ((unsigned)idx * 2654435761u) >> 23;
    int k = hkey[h];
    while (k >= 0) {
        if (k == idx) return hval[h];
        h = (h + 1) & HMASK;
        k = hkey[h];
    }
    return 0.0f;
}

// ---------------- K0: zero scratch ----------------
__global__ void init_kernel() {
    int i = threadIdx.x;
    if (i < NB) { g_cnt[i] = 0; g_zpart[i] = 0.0f; }
}

// ---------------- K1: stream half-rows ----------------
__global__ __launch_bounds__(TPB, 2)
void stream_kernel(const float* __restrict__ logits,
                   const float* __restrict__ temps,
                   float* __restrict__ out)
{
    const int b    = blockIdx.x >> 1;
    const int half = blockIdx.x & 1;
    const int tid  = threadIdx.x;
    const int lane = tid & 31;
    const int wid  = tid >> 5;
    const float invT = 1.0f / temps[b];

    const float4* lg4 = reinterpret_cast<const float4*>(logits + (size_t)b * NV) + half * NVH4;
    float4* o4 = reinterpret_cast<float4*>(out + (size_t)b * NV) + half * NVH4;
    unsigned long long* cand = g_cand + (size_t)b * GCAPB;
    const int eoff = half * NVH4 * 4;                // element offset within row
    const float4 z4 = make_float4(0.f, 0.f, 0.f, 0.f);

    float z0 = 0.f, z1 = 0.f;

    // warp-aggregated candidate push (one global atomic per nonzero ballot)
    #define PUSHC(XV, IDX)                                                            \
        {                                                                             \
            unsigned m_ = __ballot_sync(0xffffffffu, (XV) > LB0);                     \
            if (m_) {                                                                 \
                int ldr_ = __ffs(m_) - 1;                                             \
                unsigned base_ = 0;                                                   \
                if (lane == ldr_) base_ = atomicAdd(&g_cnt[b], (unsigned)__popc(m_)); \
                base_ = __shfl_sync(0xffffffffu, base_, ldr_);                        \
                if ((XV) > LB0) {                                                     \
                    unsigned p_ = base_ + __popc(m_ & ((1u << lane) - 1u));           \
                    if (p_ < GCAPB)                                                   \
                        cand[p_] = ((unsigned long long)__float_as_uint(XV) << 32)    \
                                   | (unsigned)(~(unsigned)(IDX));                    \
                }                                                                     \
            }                                                                         \
        }
    #define PUSHQ(X4, BIDX)                                                           \
        {                                                                             \
            float m4_ = fmaxf(fmaxf((X4).x, (X4).y), fmaxf((X4).z, (X4).w));          \
            if (__any_sync(0xffffffffu, m4_ > LB0)) {                                 \
                PUSHC((X4).x, (BIDX)+0) PUSHC((X4).y, (BIDX)+1)                       \
                PUSHC((X4).z, (BIDX)+2) PUSHC((X4).w, (BIDX)+3)                       \
            }                                                                         \
        }

    // unroll-2; 16000 and the 640-tail boundary are warp-aligned, so warp-uniform trips
    int v = tid;
    for (; v + TPB < NVH4; v += 2*TPB) {
        float4 x0 = lg4[v];
        float4 x1 = lg4[v + TPB];
        o4[v] = z4; o4[v + TPB] = z4;
        z0 += __expf(x0.x*invT) + __expf(x0.y*invT) + __expf(x0.z*invT) + __expf(x0.w*invT);
        z1 += __expf(x1.x*invT) + __expf(x1.y*invT) + __expf(x1.z*invT) + __expf(x1.w*invT);
        PUSHQ(x0, eoff + 4*v)
        PUSHQ(x1, eoff + 4*(v + TPB))
    }
    for (; v < NVH4; v += TPB) {
        float4 x0 = lg4[v];
        o4[v] = z4;
        z0 += __expf(x0.x*invT) + __expf(x0.y*invT) + __expf(x0.z*invT) + __expf(x0.w*invT);
        PUSHQ(x0, eoff + 4*v)
    }
    #undef PUSHC
    #undef PUSHQ

    // block-reduce partial Z, one commutative atomicAdd per CTA (2 per row -> deterministic)
    __shared__ float sred[32];
    float z = z0 + z1;
    for (int o = 16; o; o >>= 1) z += __shfl_xor_sync(0xffffffffu, z, o);
    if (lane == 0) sred[wid] = z;
    __syncthreads();
    if (wid == 0) {
        float r = sred[lane];
        for (int o = 16; o; o >>= 1) r += __shfl_xor_sync(0xffffffffu, r, o);
        if (lane == 0) atomicAdd(&g_zpart[b], r);
    }
}

// ---------------- K2: filter + select + scatter ----------------
__global__ __launch_bounds__(TPB, 1)
void select_kernel(const float* __restrict__ logits,
                   const int* __restrict__ toks,
                   const float* __restrict__ presp,
                   const float* __restrict__ freqp,
                   const float* __restrict__ temps,
                   const float* __restrict__ topps,
                   const int* __restrict__ topks,
                   float* __restrict__ out)
{
    extern __shared__ char dyn_raw[];
    DynSmem* ds = reinterpret_cast<DynSmem*>(dyn_raw);
    unsigned* s_hist = ds->hist;
    float* s_whist = ds->whist;
    unsigned long long* s_candA = ds->candA;
    unsigned long long* s_candB = ds->candB;
    unsigned long long* s_gath = ds->gath;

    __shared__ int   s_hkey[HSZ];
    __shared__ float s_hval[HSZ];
    __shared__ float s_redf[32];
    __shared__ unsigned s_redu[32];
    __shared__ float s_Z, s_WexclK, s_WexclP, s_Wtot, s_S;
    __shared__ unsigned s_cntA, s_cnt2, s_gcnt, s_bK, s_bP, s_CntB;
    __shared__ unsigned long long s_cut;

    const int tid  = threadIdx.x;
    const int lane = tid & 31;
    const int wid  = tid >> 5;
    const int b    = blockIdx.x;

    const float invT = 1.0f / temps[b];
    const float fpen = freqp[b];
    const float ppen = presp[b];
    const float tp   = topps[b];
    const int   Ksel = topks[b];
    const unsigned K = (unsigned)Ksel;

    // ---- penalty hash ----
    for (int i = tid; i < HSZ; i += TPB) { s_hkey[i] = -1; ((int*)s_hval)[i] = 0; }
    __syncthreads();
    if (tid < NL) {
        int tok = toks[(size_t)b * NL + tid];
        unsigned h = ((unsigned)tok * 2654435761u) >> 23;
        for (;;) {
            int prev = atomicCAS(&s_hkey[h], -1, tok);
            if (prev == -1 || prev == tok) { atomicAdd((int*)&s_hval[h], 1); break; }
            h = (h + 1) & HMASK;
        }
    }
    __syncthreads();
    for (int i = tid; i < HSZ; i += TPB) {
        if (s_hkey[i] >= 0) {
            int c = ((int*)s_hval)[i];
            s_hval[i] = fpen * (float)c + ppen;
        }
    }
    __syncthreads();

    // ---- Z = K1 partial + penalty fixup ----
    float zfix = 0.0f;
    for (int i = tid; i < HSZ; i += TPB) {
        int tok = s_hkey[i];
        if (tok >= 0) {
            float x = logits[(size_t)b * NV + tok];
            float a = s_hval[i];
            zfix += __expf((x - a) * invT) - __expf(x * invT);
        }
    }
    for (int o = 16; o; o >>= 1) zfix += __shfl_xor_sync(0xffffffffu, zfix, o);
    if (lane == 0) s_redf[wid] = zfix;
    __syncthreads();
    if (wid == 0) {
        float r = s_redf[lane];
        for (int o = 16; o; o >>= 1) r += __shfl_xor_sync(0xffffffffu, r, o);
        if (lane == 0) s_Z = r + g_zpart[b];
    }
    __syncthreads();
    const float tpZ = tp * s_Z;

    const float4* lg4 = reinterpret_cast<const float4*>(logits + (size_t)b * NV);
    const unsigned cntRaw = g_cnt[b];
    float LB = LB0;
    float hsc = (float)NBINS / (HIW - LB);
    unsigned cntEff = 0;
    bool ok = false;
    bool over = cntRaw > CAPB;

    #define FILTER_ONE(KEY)                                                           \
        {                                                                             \
            unsigned long long key_ = (KEY);                                          \
            float xv_ = __uint_as_float((unsigned)(key_ >> 32));                      \
            int idx_ = (int)(~(unsigned)key_);                                        \
            float a_  = hlookup(idx_, s_hkey, s_hval);                                \
            float xp_ = xv_ - a_;                                                     \
            if (xp_ > LB) {                                                           \
                int ids_ = (int)((HIW - xp_) * hsc);                                  \
                ids_ = min(max(ids_, 0), NBINS - 1);                                  \
                atomicAdd(&s_hist[ids_], 1u);                                         \
                atomicAdd(&s_whist[ids_], __expf(xp_ * invT));                        \
                unsigned pos_ = atomicAdd(&s_cnt2, 1u);                               \
                if (pos_ < CAPB)                                                      \
                    s_candB[pos_] = ((unsigned long long)__float_as_uint(xp_) << 32)  \
                                    | (unsigned)(~(unsigned)idx_);                    \
            }                                                                         \
        }

    // ---- fast path: filter K1's global candidate buffer (L2-resident) ----
    if (!over) {
        for (int i = tid; i < NBINS; i += TPB) { s_hist[i] = 0; s_whist[i] = 0.0f; }
        if (tid == 0) s_cnt2 = 0;
        __syncthreads();
        const unsigned long long* cand = g_cand + (size_t)b * GCAPB;
        for (unsigned i = tid; i < cntRaw; i += TPB) FILTER_ONE(cand[i])
        __syncthreads();
        if (s_cnt2 >= K) { ok = true; cntEff = s_cnt2; }
    }

    // ---- slow path (essentially never): full-row rescan ladder ----
    for (int att = 0; att < 3 && !ok; att++) {
        LB = over ? (LB + 0.15f) : (LB - 0.5f);
        hsc = (float)NBINS / (HIW - LB);
        for (int i = tid; i < NBINS; i += TPB) { s_hist[i] = 0; s_whist[i] = 0.0f; }
        if (tid == 0) { s_cntA = 0; s_cnt2 = 0; }
        __syncthreads();
        for (int v = tid; v < NV4; v += TPB) {
            float4 x0 = lg4[v];
            float m4 = fmaxf(fmaxf(x0.x, x0.y), fmaxf(x0.z, x0.w));
            if (m4 > LB) {
                int base = v * 4;
                float xs[4] = {x0.x, x0.y, x0.z, x0.w};
                #pragma unroll
                for (int c = 0; c < 4; c++) {
                    if (xs[c] > LB) {
                        unsigned pos = atomicAdd(&s_cntA, 1u);
                        if (pos < CAPB)
                            s_candA[pos] = ((unsigned long long)__float_as_uint(xs[c]) << 32)
                                           | (unsigned)(~(unsigned)(base + c));
                    }
                }
            }
        }
        __syncthreads();
        unsigned rawA = s_cntA;
        over = rawA > CAPB;
        unsigned cntA = min(rawA, (unsigned)CAPB);
        for (unsigned i = tid; i < cntA; i += TPB) FILTER_ONE(s_candA[i])
        __syncthreads();
        unsigned c2 = min(s_cnt2, (unsigned)CAPB);
        if ((!over && c2 >= K) || att == 2) { ok = true; cntEff = c2; }
    }
    cntEff = min(cntEff, (unsigned)CAPB);
    #undef FILTER_ONE

    if (tid == 0) { s_bK = NBINS; s_bP = NBINS; s_CntB = 0; }
    __syncthreads();

    // ---- fused count+weight scan: bK, CntB, WexclK, bP, WexclP, Wtot ----
    {
        unsigned c0 = s_hist[tid*4+0], c1 = s_hist[tid*4+1], c2 = s_hist[tid*4+2], c3 = s_hist[tid*4+3];
        float    f0 = s_whist[tid*4+0], f1 = s_whist[tid*4+1], f2 = s_whist[tid*4+2], f3 = s_whist[tid*4+3];
        unsigned u0 = c0, u1 = u0+c1, u2 = u1+c2, u3 = u2+c3;
        float    g0 = f0, g1 = g0+f1, g2 = g1+f2, g3 = g2+f3;
        unsigned utsum = u3; float ftsum = g3;
        unsigned uincl = utsum; float fincl = ftsum;
        for (int o = 1; o < 32; o <<= 1) {
            unsigned tu = __shfl_up_sync(0xffffffffu, uincl, o);
            float    tf = __shfl_up_sync(0xffffffffu, fincl, o);
            if (lane >= o) { uincl += tu; fincl += tf; }
        }
        if (lane == 31) { s_redu[wid] = uincl; s_redf[wid] = fincl; }
        __syncthreads();
        if (wid == 0) {
            unsigned wu = s_redu[lane], wui = wu;
            float    wf = s_redf[lane], wfi = wf;
            for (int o = 1; o < 32; o <<= 1) {
                unsigned tu = __shfl_up_sync(0xffffffffu, wui, o);
                float    tf = __shfl_up_sync(0xffffffffu, wfi, o);
                if (lane >= o) { wui += tu; wfi += tf; }
            }
            s_redu[lane] = wui - wu;
            s_redf[lane] = wfi - wf;
        }
        __syncthreads();
        unsigned ustart = (uincl - utsum) + s_redu[wid];
        float    fstart = (fincl - ftsum) + s_redf[wid];
        if (ustart < K && ustart + utsum >= K) {
            if      (ustart + u0 >= K) { s_bK = tid*4+0; s_CntB = ustart;      s_WexclK = fstart; }
            else if (ustart + u1 >= K) { s_bK = tid*4+1; s_CntB = ustart + u0; s_WexclK = fstart + g0; }
            else if (ustart + u2 >= K) { s_bK = tid*4+2; s_CntB = ustart + u1; s_WexclK = fstart + g1; }
            else                       { s_bK = tid*4+3; s_CntB = ustart + u2; s_WexclK = fstart + g2; }
        }
        if (fstart <= tpZ && fstart + ftsum > tpZ) {
            if      (fstart + g0 > tpZ) { s_bP = tid*4+0; s_WexclP = fstart; }
            else if (fstart + g1 > tpZ) { s_bP = tid*4+1; s_WexclP = fstart + g0; }
            else if (fstart + g2 > tpZ) { s_bP = tid*4+2; s_WexclP = fstart + g1; }
            else                        { s_bP = tid*4+3; s_WexclP = fstart + g2; }
        }
        if (tid == TPB-1) s_Wtot = fstart + ftsum;
    }
    __syncthreads();

    const unsigned bK   = s_bK;
    const unsigned bP   = s_bP;
    const unsigned bcut = min(bK, bP);

    if (bcut >= NBINS) {
        if (tid == 0) { s_S = s_Wtot; s_cut = 0ull; }
        __syncthreads();
    } else {
        if (tid == 0) s_gcnt = 0;
        __syncthreads();
        for (unsigned i = tid; i < cntEff; i += TPB) {
            unsigned long long key = s_candB[i];
            float xp = __uint_as_float((unsigned)(key >> 32));
            int ids = (int)((HIW - xp) * hsc);
            ids = min(max(ids, 0), NBINS - 1);
            if ((unsigned)ids == bcut) {
                unsigned pos = atomicAdd(&s_gcnt, 1u);
                if (pos < GCAP) s_gath[pos] = key;
            }
        }
        __syncthreads();
        unsigned g = min(s_gcnt, (unsigned)GCAP);
        unsigned P = 2; while (P < g) P <<= 1;
        for (unsigned i = tid; i < P; i += TPB) if (i >= g) s_gath[i] = 0ull;
        __syncthreads();
        for (unsigned k = 2; k <= P; k <<= 1) {
            for (unsigned j = k >> 1; j > 0; j >>= 1) {
                for (unsigned i = tid; i < P; i += TPB) {
                    unsigned l = i ^ j;
                    if (l > i) {
                        unsigned long long a = s_gath[i], bb = s_gath[l];
                        bool desc = ((i & k) == 0);
                        if (desc ? (a < bb) : (a > bb)) { s_gath[i] = bb; s_gath[l] = a; }
                    }
                }
                __syncthreads();
            }
        }
        if (tid == 0) {
            float e = (bcut == bK) ? s_WexclK : s_WexclP;
            unsigned kmax = (bcut == bK) ? (K - s_CntB) : 0xffffffffu;
            unsigned kept = 0;
            while (kept < g && kept < kmax) {
                if (e > tpZ) break;               // exclusive cumsum > top_p*Z -> stop
                float xp = __uint_as_float((unsigned)(s_gath[kept] >> 32));
                e += __expf(xp * invT);
                kept++;
            }
            s_S = e;
            s_cut = kept ? s_gath[kept-1] : 0xffffffffffffffffull;
        }
        __syncthreads();
    }

    const float invS = 1.0f / s_S;
    const unsigned long long cut = s_cut;

    // ---- scatter kept probs (out already zero-filled by K1) ----
    for (unsigned i = tid; i < cntEff; i += TPB) {
        unsigned long long key = s_candB[i];
        float xp = __uint_as_float((unsigned)(key >> 32));
        int ids = (int)((HIW - xp) * hsc);
        ids = min(max(ids, 0), NBINS - 1);
        bool keep = ((unsigned)ids < bcut) || ((unsigned)ids == bcut && key >= cut);
        if (keep) {
            unsigned idx = ~(unsigned)key;
            out[(size_t)b * NV + idx] = __expf(xp * invT) * invS;
        }
    }
}

extern "C" void kernel_launch(void* const* d_in, const int* in_sizes, int n_in,
                              void* d_out, int out_size) {
    static bool attr_set = false;
    if (!attr_set) {
        cudaFuncSetAttribute(select_kernel, cudaFuncAttributeMaxDynamicSharedMemorySize, SMEM_DYN);
        attr_set = true;
    }
    const float* logits = (const float*)d_in[0];
    const int*   toks   = (const int*)d_in[1];
    const float* pres   = (const float*)d_in[2];
    const float* freq   = (const float*)d_in[3];
    const float* temps  = (const float*)d_in[4];
    const float* topps  = (const float*)d_in[5];
    const int*   topks  = (const int*)d_in[6];
    float* out = (float*)d_out;
    init_kernel<<<1, NB>>>();
    stream_kernel<<<NB * 2, TPB>>>(logits, temps, out);
    select_kernel<<<NB, TPB, SMEM_DYN>>>(logits, toks, pres, freq, temps, topps, topks, out);
}